// round 5
// baseline (speedup 1.0000x reference)
#include <cuda_runtime.h>

// Problem constants (fixed by the reference).
#define NB 4096
#define NT 512
#define NI 5
#define XST 8                 // padded x-row stride (32B -> LDS.128-aligned)
#define NH 16
#define FULLMASK 0xffffffffu

typedef unsigned long long ull;

// ---- fast activations ----
__device__ __forceinline__ float tanh_fast(float x) {
    float y;
    asm("tanh.approx.f32 %0, %1;" : "=f"(y) : "f"(x));
    return y;
}
__device__ __forceinline__ float sig_acc(float x) {   // epilogue only
    float e = __expf(-x);
    return __fdividef(1.0f, 1.0f + e);
}

// ---- packed f32x2 helpers (Blackwell FFMA2) ----
__device__ __forceinline__ ull pack2(float lo, float hi) {
    ull r;
    asm("mov.b64 %0, {%1, %2};" : "=l"(r) : "f"(lo), "f"(hi));
    return r;
}
__device__ __forceinline__ void unpack2(ull v, float& lo, float& hi) {
    asm("mov.b64 {%0, %1}, %2;" : "=f"(lo), "=f"(hi) : "l"(v));
}
__device__ __forceinline__ void fma2(ull& acc, ull a, ull b) {
    asm("fma.rn.f32x2 %0, %1, %2, %0;" : "+l"(acc) : "l"(a), "l"(b));
}
__device__ __forceinline__ ull add2(ull a, ull b) {
    ull r;
    asm("add.rn.f32x2 %0, %1, %2;" : "=l"(r) : "l"(a), "l"(b));
    return r;
}

// Single-warp LSTM over the ONLY batch row that matters (b = NB-1).
// Lane L owns gate L (i for L<16, f for L>=16) and gate L+32 (g / o).
// h-vector is broadcast through smem: STS + BAR.SYNC (3-7 cyc @ 1 warp,
// drains STS) + LDS.128 -> aligned f32x2 pairs, zero pack MOVs.
__global__ void __launch_bounds__(32, 1) lstm_last_row_kernel(
    const float* __restrict__ x,      // (B, T, I)
    const float* __restrict__ W_ih,   // (64, 5)
    const float* __restrict__ W_hh,   // (64, 16)
    const float* __restrict__ b_ih,   // (64,)
    const float* __restrict__ b_hh,   // (64,)
    const float* __restrict__ W_lin,  // (5, 16)
    const float* __restrict__ b_lin,  // (5,)
    float* __restrict__ out)          // (5,)
{
    __shared__ __align__(16) float xs[NT * XST];   // 16 KB, padded rows
    __shared__ __align__(16) float hs[32];         // h state (lower 16 live)

    const int lane = threadIdx.x;

    // Stage x[B-1, :, :] into padded smem rows (one-time, latency-tolerant).
    {
        const float* src = x + (size_t)(NB - 1) * NT * NI;
        #pragma unroll 4
        for (int i = lane; i < NT * NI; i += 32) {
            const int t = i / NI, j = i - t * NI;
            xs[t * XST + j] = src[i];
        }
    }
    hs[lane] = 0.0f;

    const int g0 = lane;        // i_k (lane<16) or f_k (lane>=16)
    const int g1 = lane + 32;   // g_k (lane<16) or o_k (lane>=16)

    // Recurrent weights, packed in (even,odd) f32x2 pairs.
    ull wA2[NH / 2], wB2[NH / 2];
    #pragma unroll
    for (int p = 0; p < NH / 2; ++p) {
        wA2[p] = pack2(W_hh[g0 * NH + 2 * p], W_hh[g0 * NH + 2 * p + 1]);
        wB2[p] = pack2(W_hh[g1 * NH + 2 * p], W_hh[g1 * NH + 2 * p + 1]);
    }
    float wiA[NI], wiB[NI];
    #pragma unroll
    for (int i = 0; i < NI; ++i) {
        wiA[i] = W_ih[g0 * NI + i];
        wiB[i] = W_ih[g1 * NI + i];
    }
    const float bbA = b_ih[g0] + b_hh[g0];
    const float bbB = b_ih[g1] + b_hh[g1];

    // thA = tanh(0.5*gA) for all lanes (i and f are both sigmoids).
    // thB = tanh(aB*gB): g (lane<16) wants tanh(x) -> aB=1;
    //                    o (lane>=16) is sigmoid   -> aB=0.5.
    const float aB = (lane < 16) ? 1.0f : 0.5f;

    float c = 0.0f;

    __syncthreads();   // xs + hs init visible

    #pragma unroll 4
    for (int t = 0; t < NT; ++t) {
        // Input projection (h-independent; fills issue bubbles).
        const float4 xq = *reinterpret_cast<const float4*>(&xs[t * XST]);
        const float  x4 = xs[t * XST + 4];
        float a0 = bbA, a1 = bbB;
        a0 = fmaf(wiA[0], xq.x, a0);  a1 = fmaf(wiB[0], xq.x, a1);
        a0 = fmaf(wiA[1], xq.y, a0);  a1 = fmaf(wiB[1], xq.y, a1);
        a0 = fmaf(wiA[2], xq.z, a0);  a1 = fmaf(wiB[2], xq.z, a1);
        a0 = fmaf(wiA[3], xq.w, a0);  a1 = fmaf(wiB[3], xq.w, a1);
        a0 = fmaf(wiA[4], x4,   a0);  a1 = fmaf(wiB[4], x4,   a1);

        // h-vector: 4x LDS.128 as pre-packed f32x2 pairs.
        // hpP holds (h[4P..4P+1], h[4P+2..4P+3]) and pairs with wA2[2P..2P+1].
        const ulonglong2 hpA = *reinterpret_cast<const ulonglong2*>(&hs[0]);
        const ulonglong2 hpB = *reinterpret_cast<const ulonglong2*>(&hs[4]);

        // Recurrent matvec: 16 packed FMAs, 4 split chains (depth 4).
        ull accA0 = pack2(a0, 0.0f), accA1 = pack2(0.0f, 0.0f);
        ull accB0 = pack2(a1, 0.0f), accB1 = pack2(0.0f, 0.0f);
        fma2(accA0, wA2[0], hpA.x);  fma2(accB0, wB2[0], hpA.x);
        fma2(accA1, wA2[1], hpA.y);  fma2(accB1, wB2[1], hpA.y);
        fma2(accA0, wA2[2], hpB.x);  fma2(accB0, wB2[2], hpB.x);
        fma2(accA1, wA2[3], hpB.y);  fma2(accB1, wB2[3], hpB.y);
        const ulonglong2 hpC = *reinterpret_cast<const ulonglong2*>(&hs[8]);
        const ulonglong2 hpD = *reinterpret_cast<const ulonglong2*>(&hs[12]);
        fma2(accA0, wA2[4], hpC.x);  fma2(accB0, wB2[4], hpC.x);
        fma2(accA1, wA2[5], hpC.y);  fma2(accB1, wB2[5], hpC.y);
        fma2(accA0, wA2[6], hpD.x);  fma2(accB0, wB2[6], hpD.x);
        fma2(accA1, wA2[7], hpD.y);  fma2(accB1, wB2[7], hpD.y);

        const ull accA = add2(accA0, accA1);
        const ull accB = add2(accB0, accB1);
        float xA, yA, xB, yB;
        unpack2(accA, xA, yA);
        unpack2(accB, xB, yB);

        // Activations: one MUFU.TANH per half.
        const float thA = tanh_fast(0.5f * (xA + yA));   // -> sig(i) | sig(f)
        const float thB = tanh_fast(aB * (xB + yB));     // -> tanh(g) | sig(o)

        // Ship f/o tanh-halves down to the state lanes.
        const float thF = __shfl_down_sync(FULLMASK, thA, 16);
        const float thO = __shfl_down_sync(FULLMASK, thB, 16);

        // Cell update (real state in lanes 0..15; upper lanes compute junk).
        const float si = fmaf(0.5f, thA, 0.5f);   // sigmoid(i)
        const float ig = si * thB;                // i * g
        const float sf = fmaf(0.5f, thF, 0.5f);   // sigmoid(f)
        c = fmaf(sf, c, ig);
        const float tc = tanh_fast(c);
        const float so = fmaf(0.5f, thO, 0.5f);   // sigmoid(o)
        const float h  = so * tc;

        hs[lane] = h;       // all 32 lanes store; only 0..15 ever read
        __syncthreads();    // 1-warp BAR: ~3-7 cyc, drains STS
    }

    // Epilogue (off-chain, accurate math). h vector already in hs[0..15].
    if (lane < 5) {
        float acc = b_lin[lane];
        #pragma unroll
        for (int k = 0; k < NH; ++k)
            acc = fmaf(W_lin[lane * NH + k], hs[k], acc);
        out[lane] = sig_acc(acc);
    }
}

extern "C" void kernel_launch(void* const* d_in, const int* in_sizes, int n_in,
                              void* d_out, int out_size) {
    (void)in_sizes; (void)n_in; (void)out_size;
    const float* x     = (const float*)d_in[0];
    const float* W_ih  = (const float*)d_in[1];
    const float* W_hh  = (const float*)d_in[2];
    const float* b_ih  = (const float*)d_in[3];
    const float* b_hh  = (const float*)d_in[4];
    const float* W_lin = (const float*)d_in[5];
    const float* b_lin = (const float*)d_in[6];
    float* out = (float*)d_out;

    lstm_last_row_kernel<<<1, 32>>>(x, W_ih, W_hh, b_ih, b_hh, W_lin, b_lin, out);
}